// round 1
// baseline (speedup 1.0000x reference)
#include <cuda_runtime.h>
#include <cuda_bf16.h>
#include <cstddef>

// ---------------------------------------------------------------------------
// GHM (Graph HyperMixer) — fp32 baseline, fully fused pipeline.
//   Per block:
//     Hf   = gelu(X @ ff1_w + b)                  (N,256)
//     G    = gelu(Hf @ wA)                        (N,256)
//     Wt   = G @ wB                               (N,64)
//     S    = Hf^T @ Wt   (split-K, deterministic) (256,64)
//     At   = gelu(S)^T                            (64,256)
//     Hf  := gelu(Hf)    (in-place, after S uses raw Hf)
//     P    = gelu(Wt @ At)                        (N,256)
//     Xo   = P @ ff2[0:256] + b                   (N,256)
//     Xo  += Hf @ ff2[256:512]                    (N,256)
//   Then mean over N (two-stage deterministic) + head.
// ---------------------------------------------------------------------------

#define NMAX 200000
#define HDIM 256
#define MDIM 64

__device__ float g_Hf [(size_t)NMAX * HDIM];
__device__ float g_G  [(size_t)NMAX * HDIM];
__device__ float g_X  [(size_t)NMAX * HDIM];
__device__ float g_Wt [(size_t)NMAX * MDIM];
__device__ float g_part[256 * HDIM * MDIM];   // split-K partials for S
__device__ float g_At [MDIM * HDIM];          // gelu(S)^T
__device__ float g_mp [256 * HDIM];           // mean partials

__device__ __forceinline__ float gelu_f(float x) {
    return 0.5f * x * (1.0f + erff(x * 0.70710678118654752440f));
}

// ---------------------------------------------------------------------------
// Generic tiled GEMM: C = op(A@B [+bias]) [+C]
// A: (M,K) row-major, B: (K,Nc) row-major, C: (M,Nc) row-major.
// Tile: BM=128 x BN=64 x BK=16, 256 threads, 8x4 microtile.
// Requires K % 16 == 0, Nc % 64 == 0 (true for all our shapes).
// ---------------------------------------------------------------------------
#define BM 128
#define BN 64
#define BK 16

template<bool POST_GELU, bool HAS_BIAS, bool ACC>
__global__ __launch_bounds__(256)
void gemm_kernel(const float* __restrict__ A, const float* __restrict__ B,
                 const float* __restrict__ bias, float* __restrict__ C,
                 int M, int K, int Nc)
{
    __shared__ float As[BK][BM];   // [k][m]
    __shared__ float Bs[BK][BN];   // [k][n]

    const int t    = threadIdx.x;
    const int row0 = blockIdx.x * BM;
    const int col0 = blockIdx.y * BN;
    const int tx   = t & 15;       // 16 col-groups of 4
    const int ty   = t >> 4;       // 16 row-groups of 8

    float acc[8][4];
    #pragma unroll
    for (int i = 0; i < 8; i++)
        #pragma unroll
        for (int j = 0; j < 4; j++) acc[i][j] = 0.0f;

    for (int k0 = 0; k0 < K; k0 += BK) {
        // Load A tile: 128x16 floats = 512 float4, 2 per thread, stored transposed.
        #pragma unroll
        for (int i = 0; i < 2; i++) {
            int idx = t + i * 256;           // 0..511
            int r   = idx >> 2;              // 0..127
            int c4  = (idx & 3) << 2;        // 0,4,8,12
            float4 v = make_float4(0.f, 0.f, 0.f, 0.f);
            int gr = row0 + r;
            if (gr < M)
                v = *reinterpret_cast<const float4*>(&A[(size_t)gr * K + k0 + c4]);
            As[c4 + 0][r] = v.x;
            As[c4 + 1][r] = v.y;
            As[c4 + 2][r] = v.z;
            As[c4 + 3][r] = v.w;
        }
        // Load B tile: 16x64 floats = 256 float4, 1 per thread.
        {
            int r  = t >> 4;                 // 0..15
            int c4 = (t & 15) << 2;          // 0..60
            float4 v = *reinterpret_cast<const float4*>(
                &B[(size_t)(k0 + r) * Nc + col0 + c4]);
            *reinterpret_cast<float4*>(&Bs[r][c4]) = v;
        }
        __syncthreads();

        #pragma unroll
        for (int kk = 0; kk < BK; kk++) {
            float a[8], b[4];
            #pragma unroll
            for (int i = 0; i < 8; i++) a[i] = As[kk][ty * 8 + i];
            #pragma unroll
            for (int j = 0; j < 4; j++) b[j] = Bs[kk][tx * 4 + j];
            #pragma unroll
            for (int i = 0; i < 8; i++)
                #pragma unroll
                for (int j = 0; j < 4; j++)
                    acc[i][j] = fmaf(a[i], b[j], acc[i][j]);
        }
        __syncthreads();
    }

    float b4[4] = {0.f, 0.f, 0.f, 0.f};
    if (HAS_BIAS) {
        #pragma unroll
        for (int j = 0; j < 4; j++) b4[j] = bias[col0 + tx * 4 + j];
    }

    #pragma unroll
    for (int i = 0; i < 8; i++) {
        int gr = row0 + ty * 8 + i;
        if (gr >= M) continue;
        size_t off = (size_t)gr * Nc + col0 + tx * 4;
        float4 v;
        float r0 = acc[i][0], r1 = acc[i][1], r2 = acc[i][2], r3 = acc[i][3];
        if (HAS_BIAS) { r0 += b4[0]; r1 += b4[1]; r2 += b4[2]; r3 += b4[3]; }
        if (POST_GELU) { r0 = gelu_f(r0); r1 = gelu_f(r1); r2 = gelu_f(r2); r3 = gelu_f(r3); }
        if (ACC) {
            float4 c = *reinterpret_cast<const float4*>(&C[off]);
            r0 += c.x; r1 += c.y; r2 += c.z; r3 += c.w;
        }
        v.x = r0; v.y = r1; v.z = r2; v.w = r3;
        *reinterpret_cast<float4*>(&C[off]) = v;
    }
}

// ---------------------------------------------------------------------------
// S partials: part[blk][h][m] = sum over this block's row chunk of Hf[r,h]*Wt[r,m]
// 256 blocks, 256 threads (thread = h). Deterministic split-K.
// ---------------------------------------------------------------------------
__global__ __launch_bounds__(256)
void spartial_kernel(const float* __restrict__ Hf, const float* __restrict__ Wt,
                     float* __restrict__ part, int N)
{
    __shared__ float ws[8 * MDIM];
    const int t     = threadIdx.x;
    const int blk   = blockIdx.x;
    const int chunk = (N + 255) / 256;
    const int rbeg  = blk * chunk;
    const int rend  = min(N, rbeg + chunk);

    float acc[MDIM];
    #pragma unroll
    for (int m = 0; m < MDIM; m++) acc[m] = 0.0f;

    for (int r = rbeg; r < rend; r += 8) {
        int nr = min(8, rend - r);
        __syncthreads();
        for (int i = t; i < nr * MDIM; i += 256)
            ws[i] = Wt[(size_t)r * MDIM + i];
        __syncthreads();
        for (int rr = 0; rr < nr; rr++) {
            float hv = Hf[(size_t)(r + rr) * HDIM + t];
            #pragma unroll
            for (int m = 0; m < MDIM; m++)
                acc[m] = fmaf(hv, ws[rr * MDIM + m], acc[m]);
        }
    }
    float* p = part + (size_t)blk * HDIM * MDIM + (size_t)t * MDIM;
    #pragma unroll
    for (int m = 0; m < MDIM; m++) p[m] = acc[m];
}

// Sum the 256 partials, gelu, write TRANSPOSED: At[m][h] = gelu(S[h][m]).
__global__ __launch_bounds__(256)
void sfinal_kernel(const float* __restrict__ part, float* __restrict__ At)
{
    int idx = blockIdx.x * 256 + threadIdx.x;    // 0..16383 (64 blocks)
    float s = 0.0f;
    for (int p = 0; p < 256; p++)
        s += part[(size_t)p * HDIM * MDIM + idx];
    int h = idx >> 6, m = idx & 63;
    At[m * HDIM + h] = gelu_f(s);
}

// In-place gelu (vectorized).
__global__ void gelu_inplace_kernel(float* __restrict__ X, int n4)
{
    int i = blockIdx.x * blockDim.x + threadIdx.x;
    if (i < n4) {
        float4 v = reinterpret_cast<float4*>(X)[i];
        v.x = gelu_f(v.x); v.y = gelu_f(v.y); v.z = gelu_f(v.z); v.w = gelu_f(v.w);
        reinterpret_cast<float4*>(X)[i] = v;
    }
}

// Mean partials: part[blk][h] = sum over row chunk of X[r,h].
__global__ __launch_bounds__(256)
void meanpart_kernel(const float* __restrict__ X, float* __restrict__ part, int N)
{
    const int t     = threadIdx.x;
    const int blk   = blockIdx.x;
    const int chunk = (N + 255) / 256;
    const int rbeg  = blk * chunk;
    const int rend  = min(N, rbeg + chunk);
    float acc = 0.0f;
    for (int r = rbeg; r < rend; r++)
        acc += X[(size_t)r * HDIM + t];
    part[blk * HDIM + t] = acc;
}

// Final head: out[c] = head_b[c] + (mean vector) @ head_w.
__global__ __launch_bounds__(256)
void head_kernel(const float* __restrict__ part, const float* __restrict__ hw,
                 const float* __restrict__ hb, float* __restrict__ out, int N)
{
    __shared__ float s[HDIM];
    int t = threadIdx.x;
    float a = 0.0f;
    for (int p = 0; p < 256; p++) a += part[p * HDIM + t];
    s[t] = a * (1.0f / (float)N);
    __syncthreads();
    if (t < 64) {
        float o = hb[t];
        #pragma unroll 8
        for (int h = 0; h < HDIM; h++)
            o = fmaf(s[h], hw[h * 64 + t], o);
        out[t] = o;
    }
}

// ---------------------------------------------------------------------------
// Host side
// ---------------------------------------------------------------------------
static void launch_gemm(const float* A, const float* B, const float* bias, float* C,
                        int M, int K, int Nc, bool post, bool hasbias, bool acc)
{
    dim3 grid((M + BM - 1) / BM, Nc / BN);
    dim3 blk(256);
    if (post && hasbias)       gemm_kernel<true,  true,  false><<<grid, blk>>>(A, B, bias, C, M, K, Nc);
    else if (post)             gemm_kernel<true,  false, false><<<grid, blk>>>(A, B, bias, C, M, K, Nc);
    else if (hasbias)          gemm_kernel<false, true,  false><<<grid, blk>>>(A, B, bias, C, M, K, Nc);
    else if (acc)              gemm_kernel<false, false, true ><<<grid, blk>>>(A, B, bias, C, M, K, Nc);
    else                       gemm_kernel<false, false, false><<<grid, blk>>>(A, B, bias, C, M, K, Nc);
}

extern "C" void kernel_launch(void* const* d_in, const int* in_sizes, int n_in,
                              void* d_out, int out_size)
{
    const float* x      = (const float*)d_in[0];
    // d_in[1] = edge_index (unused by reference)
    const float* ff1_w0 = (const float*)d_in[2];
    const float* ff1_b0 = (const float*)d_in[3];
    const float* wA0    = (const float*)d_in[4];
    const float* wB0    = (const float*)d_in[5];
    const float* ff2_w0 = (const float*)d_in[6];
    const float* ff2_b0 = (const float*)d_in[7];
    const float* ff1_w1 = (const float*)d_in[8];
    const float* ff1_b1 = (const float*)d_in[9];
    const float* wA1    = (const float*)d_in[10];
    const float* wB1    = (const float*)d_in[11];
    const float* ff2_w1 = (const float*)d_in[12];
    const float* ff2_b1 = (const float*)d_in[13];
    const float* head_w = (const float*)d_in[14];
    const float* head_b = (const float*)d_in[15];
    float* out = (float*)d_out;

    const int N = in_sizes[0] / HDIM;

    float *pHf, *pG, *pX, *pWt, *pPart, *pAt, *pMp;
    cudaGetSymbolAddress((void**)&pHf,   g_Hf);
    cudaGetSymbolAddress((void**)&pG,    g_G);
    cudaGetSymbolAddress((void**)&pX,    g_X);
    cudaGetSymbolAddress((void**)&pWt,   g_Wt);
    cudaGetSymbolAddress((void**)&pPart, g_part);
    cudaGetSymbolAddress((void**)&pAt,   g_At);
    cudaGetSymbolAddress((void**)&pMp,   g_mp);

    const int n4 = (N * HDIM) / 4;
    const int geluGrid = (n4 + 255) / 256;

    // ---------------- Block 0 ----------------
    launch_gemm(x,   ff1_w0, ff1_b0, pHf, N, HDIM, HDIM, true,  true,  false); // Hf = gelu(X@W1+b)
    launch_gemm(pHf, wA0,    nullptr, pG, N, HDIM, HDIM, true,  false, false); // G  = gelu(Hf@wA)
    launch_gemm(pG,  wB0,    nullptr, pWt, N, HDIM, MDIM, false, false, false); // Wt = G@wB
    spartial_kernel<<<256, 256>>>(pHf, pWt, pPart, N);
    sfinal_kernel<<<64, 256>>>(pPart, pAt);                                    // At = gelu(S)^T
    gelu_inplace_kernel<<<geluGrid, 256>>>(pHf, n4);                           // Hf := gelu(Hf)
    launch_gemm(pWt, pAt,    nullptr, pG, N, MDIM, HDIM, true,  false, false); // P  = gelu(Wt@At)
    launch_gemm(pG,  ff2_w0, ff2_b0, pX, N, HDIM, HDIM, false, true,  false);  // Xo = P@ff2_top+b
    launch_gemm(pHf, ff2_w0 + HDIM * HDIM, nullptr, pX, N, HDIM, HDIM, false, false, true); // Xo += geluHf@ff2_bot

    // ---------------- Block 1 ----------------
    launch_gemm(pX,  ff1_w1, ff1_b1, pHf, N, HDIM, HDIM, true,  true,  false);
    launch_gemm(pHf, wA1,    nullptr, pG, N, HDIM, HDIM, true,  false, false);
    launch_gemm(pG,  wB1,    nullptr, pWt, N, HDIM, MDIM, false, false, false);
    spartial_kernel<<<256, 256>>>(pHf, pWt, pPart, N);
    sfinal_kernel<<<64, 256>>>(pPart, pAt);
    gelu_inplace_kernel<<<geluGrid, 256>>>(pHf, n4);
    launch_gemm(pWt, pAt,    nullptr, pG, N, MDIM, HDIM, true,  false, false);
    launch_gemm(pG,  ff2_w1, ff2_b1, pX, N, HDIM, HDIM, false, true,  false);
    launch_gemm(pHf, ff2_w1 + HDIM * HDIM, nullptr, pX, N, HDIM, HDIM, false, false, true);

    // ---------------- Mean + head ----------------
    meanpart_kernel<<<256, 256>>>(pX, pMp, N);
    head_kernel<<<1, 256>>>(pMp, head_w, head_b, out, N);
}

// round 2
// speedup vs baseline: 1.0097x; 1.0097x over previous
#include <cuda_runtime.h>
#include <cuda_bf16.h>
#include <cstdint>
#include <cstddef>

// ---------------------------------------------------------------------------
// GHM (Graph HyperMixer) — tf32 tensor-core pipeline (mma.sync.m16n8k8).
// ---------------------------------------------------------------------------

#define NMAX 200000
#define HDIM 256
#define MDIM 64

__device__ float g_Hf [(size_t)NMAX * HDIM];
__device__ float g_G  [(size_t)NMAX * HDIM];
__device__ float g_X  [(size_t)NMAX * HDIM];
__device__ float g_Wt [(size_t)NMAX * MDIM];
__device__ float g_part[256 * HDIM * MDIM];   // split-K partials for S
__device__ float g_At [MDIM * HDIM];          // gelu(S)^T
__device__ float g_mp [256 * HDIM];           // mean partials

__device__ __forceinline__ float gelu_f(float x) {
    return 0.5f * x * (1.0f + erff(x * 0.70710678118654752440f));
}

__device__ __forceinline__ uint32_t f2tf32(float x) {
    uint32_t y;
    asm("cvt.rna.tf32.f32 %0, %1;" : "=r"(y) : "f"(x));
    return y;
}

__device__ __forceinline__ void mma_tf32(float c[4], const uint32_t a[4], const uint32_t b[2]) {
    asm volatile(
        "mma.sync.aligned.m16n8k8.row.col.f32.tf32.tf32.f32 "
        "{%0,%1,%2,%3}, {%4,%5,%6,%7}, {%8,%9}, {%0,%1,%2,%3};\n"
        : "+f"(c[0]), "+f"(c[1]), "+f"(c[2]), "+f"(c[3])
        : "r"(a[0]), "r"(a[1]), "r"(a[2]), "r"(a[3]), "r"(b[0]), "r"(b[1]));
}

// ---------------------------------------------------------------------------
// Tensor-core GEMM: C = op(A@B [+bias]) [+C]
// A: (M,K) rm, B: (K,Nc) rm, C: (M,Nc) rm.
// Tile BM=128 x BN x BK=32, 256 threads (8 warps, 4x2 warp grid).
// Shared tiles are stored PRE-PERMUTED into mma fragment layout, so the inner
// loop is pure LDS.128/LDS.64 + HMMA.
// Requires K%32==0, Nc%BN==0.
// ---------------------------------------------------------------------------
#define BM 128
#define BK 32

template<int BN, bool POST_GELU, bool HAS_BIAS, bool ACC>
__global__ __launch_bounds__(256)
void gemm_tc_kernel(const float* __restrict__ A, const float* __restrict__ B,
                    const float* __restrict__ bias, float* __restrict__ C,
                    int M, int K, int Nc)
{
    constexpr int NT = BN / 16;            // n-tiles (of 8) per warp
    // As_p[mt(8)][ks(4)][lane(32)][reg(4)]
    __shared__ __align__(16) uint32_t As_p[8 * 4 * 32 * 4];
    // Bs_p[nt(BN/8)][ks(4)][lane(32)][reg(2)]
    __shared__ __align__(16) uint32_t Bs_p[(BN / 8) * 4 * 32 * 2];

    const int t    = threadIdx.x;
    const int lane = t & 31;
    const int w    = t >> 5;
    const int wm   = w >> 1;               // 0..3
    const int wn   = w & 1;                // 0..1
    const int row0 = blockIdx.x * BM;
    const int col0 = blockIdx.y * BN;

    float acc[2][NT][4];
    #pragma unroll
    for (int i = 0; i < 2; i++)
        #pragma unroll
        for (int j = 0; j < NT; j++)
            #pragma unroll
            for (int q = 0; q < 4; q++) acc[i][j][q] = 0.0f;

    for (int k0 = 0; k0 < K; k0 += BK) {
        // ---- load A tile (128x32) into permuted fragment layout ----
        #pragma unroll
        for (int i = 0; i < 4; i++) {
            int idx = t + i * 256;          // 0..1023  (8 float4 per row)
            int r   = idx >> 3;
            int c4  = (idx & 7) * 4;
            float4 v = make_float4(0.f, 0.f, 0.f, 0.f);
            int gr = row0 + r;
            if (gr < M)
                v = *reinterpret_cast<const float4*>(&A[(size_t)gr * K + k0 + c4]);
            int mt = r >> 4, rm = r & 15;
            int ks = c4 >> 3;
            int reg = (rm >> 3) + ((c4 & 4) ? 2 : 0);
            uint32_t* dst = &As_p[(((mt * 4 + ks) * 32) + (rm & 7) * 4) * 4 + reg];
            dst[0]  = f2tf32(v.x);
            dst[4]  = f2tf32(v.y);
            dst[8]  = f2tf32(v.z);
            dst[12] = f2tf32(v.w);
        }
        // ---- load B tile (32xBN) into permuted fragment layout ----
        #pragma unroll
        for (int i = 0; i < BN / 32; i++) {
            int idx = t + i * 256;          // 0..(32*BN/4 - 1)
            int k   = idx / (BN / 4);
            int c4  = (idx % (BN / 4)) * 4;
            float4 v = *reinterpret_cast<const float4*>(
                &B[(size_t)(k0 + k) * Nc + col0 + c4]);
            int nt = c4 >> 3;
            int ks = k >> 3, kk = k & 7;
            int reg = kk >> 2;
            uint32_t* dst = &Bs_p[(((nt * 4 + ks) * 32) + ((c4 & 4) ? 16 : 0) + (kk & 3)) * 2 + reg];
            dst[0]  = f2tf32(v.x);
            dst[8]  = f2tf32(v.y);
            dst[16] = f2tf32(v.z);
            dst[24] = f2tf32(v.w);
        }
        __syncthreads();

        // ---- mma main loop ----
        #pragma unroll
        for (int ks = 0; ks < 4; ks++) {
            uint32_t a[2][4];
            #pragma unroll
            for (int i = 0; i < 2; i++)
                *reinterpret_cast<uint4*>(a[i]) =
                    *reinterpret_cast<const uint4*>(&As_p[((((wm * 2 + i) * 4 + ks) * 32) + lane) * 4]);
            uint32_t b[NT][2];
            #pragma unroll
            for (int j = 0; j < NT; j++)
                *reinterpret_cast<uint2*>(b[j]) =
                    *reinterpret_cast<const uint2*>(&Bs_p[((((wn * NT + j) * 4 + ks) * 32) + lane) * 2]);
            #pragma unroll
            for (int i = 0; i < 2; i++)
                #pragma unroll
                for (int j = 0; j < NT; j++)
                    mma_tf32(acc[i][j], a[i], b[j]);
        }
        __syncthreads();
    }

    // ---- epilogue ----
    const int g  = lane >> 2;
    const int tg = lane & 3;
    #pragma unroll
    for (int i = 0; i < 2; i++) {
        int row = row0 + wm * 32 + i * 16 + g;
        #pragma unroll
        for (int j = 0; j < NT; j++) {
            int col = col0 + wn * NT * 8 + j * 8 + tg * 2;
            float c0 = acc[i][j][0], c1 = acc[i][j][1];
            float c2 = acc[i][j][2], c3 = acc[i][j][3];
            if (HAS_BIAS) {
                float2 bb = *reinterpret_cast<const float2*>(&bias[col]);
                c0 += bb.x; c1 += bb.y; c2 += bb.x; c3 += bb.y;
            }
            if (POST_GELU) {
                c0 = gelu_f(c0); c1 = gelu_f(c1); c2 = gelu_f(c2); c3 = gelu_f(c3);
            }
            if (row < M) {
                size_t o = (size_t)row * Nc + col;
                if (ACC) {
                    float2 old = *reinterpret_cast<const float2*>(&C[o]);
                    c0 += old.x; c1 += old.y;
                }
                *reinterpret_cast<float2*>(&C[o]) = make_float2(c0, c1);
            }
            if (row + 8 < M) {
                size_t o = (size_t)(row + 8) * Nc + col;
                if (ACC) {
                    float2 old = *reinterpret_cast<const float2*>(&C[o]);
                    c2 += old.x; c3 += old.y;
                }
                *reinterpret_cast<float2*>(&C[o]) = make_float2(c2, c3);
            }
        }
    }
}

// ---------------------------------------------------------------------------
// S partials: part[blk][h][m] = sum over row chunk of Hf[r,h]*Wt[r,m]
// Thread owns 4 h-columns x 16 m values. FMA-pipe bound.
// ---------------------------------------------------------------------------
__global__ __launch_bounds__(256)
void spartial_kernel(const float* __restrict__ Hf, const float* __restrict__ Wt,
                     float* __restrict__ part, int N)
{
    __shared__ float4 ws[8 * 16];          // 8 rows x 64 floats of Wt
    const int t     = threadIdx.x;
    const int hq    = t & 63;              // h columns hq*4 .. +3
    const int mq    = t >> 6;              // m chunk   mq*16 .. +15
    const int blk   = blockIdx.x;
    const int chunk = (N + 255) / 256;
    const int rbeg  = blk * chunk;
    const int rend  = min(N, rbeg + chunk);

    float acc[4][16];
    #pragma unroll
    for (int c = 0; c < 4; c++)
        #pragma unroll
        for (int m = 0; m < 16; m++) acc[c][m] = 0.0f;

    for (int r = rbeg; r < rend; r += 8) {
        int nr = min(8, rend - r);
        __syncthreads();
        if (t < nr * 16)
            ws[t] = reinterpret_cast<const float4*>(&Wt[(size_t)r * MDIM])[t];
        __syncthreads();
        for (int rr = 0; rr < nr; rr++) {
            float4 h4 = *reinterpret_cast<const float4*>(
                &Hf[(size_t)(r + rr) * HDIM + hq * 4]);
            #pragma unroll
            for (int m4 = 0; m4 < 4; m4++) {
                float4 wv = ws[rr * 16 + mq * 4 + m4];
                #pragma unroll
                for (int c = 0; c < 4; c++) {
                    float hv = (c == 0) ? h4.x : (c == 1) ? h4.y : (c == 2) ? h4.z : h4.w;
                    acc[c][m4 * 4 + 0] = fmaf(hv, wv.x, acc[c][m4 * 4 + 0]);
                    acc[c][m4 * 4 + 1] = fmaf(hv, wv.y, acc[c][m4 * 4 + 1]);
                    acc[c][m4 * 4 + 2] = fmaf(hv, wv.z, acc[c][m4 * 4 + 2]);
                    acc[c][m4 * 4 + 3] = fmaf(hv, wv.w, acc[c][m4 * 4 + 3]);
                }
            }
        }
    }
    #pragma unroll
    for (int c = 0; c < 4; c++) {
        float* p = part + (size_t)blk * HDIM * MDIM + (size_t)(hq * 4 + c) * MDIM + mq * 16;
        #pragma unroll
        for (int m4 = 0; m4 < 4; m4++)
            *reinterpret_cast<float4*>(&p[m4 * 4]) =
                make_float4(acc[c][m4 * 4 + 0], acc[c][m4 * 4 + 1],
                            acc[c][m4 * 4 + 2], acc[c][m4 * 4 + 3]);
    }
}

// Sum the 256 partials, gelu, write TRANSPOSED: At[m][h] = gelu(S[h][m]).
__global__ __launch_bounds__(256)
void sfinal_kernel(const float* __restrict__ part, float* __restrict__ At)
{
    int idx = blockIdx.x * 256 + threadIdx.x;    // 0..16383
    float s = 0.0f;
    for (int p = 0; p < 256; p++)
        s += part[(size_t)p * HDIM * MDIM + idx];
    int h = idx >> 6, m = idx & 63;
    At[m * HDIM + h] = gelu_f(s);
}

// In-place gelu (vectorized).
__global__ void gelu_inplace_kernel(float* __restrict__ X, int n4)
{
    int i = blockIdx.x * blockDim.x + threadIdx.x;
    if (i < n4) {
        float4 v = reinterpret_cast<float4*>(X)[i];
        v.x = gelu_f(v.x); v.y = gelu_f(v.y); v.z = gelu_f(v.z); v.w = gelu_f(v.w);
        reinterpret_cast<float4*>(X)[i] = v;
    }
}

// Mean partials: part[blk][h] = sum over row chunk of X[r,h].
__global__ __launch_bounds__(256)
void meanpart_kernel(const float* __restrict__ X, float* __restrict__ part, int N)
{
    const int t     = threadIdx.x;
    const int blk   = blockIdx.x;
    const int chunk = (N + 255) / 256;
    const int rbeg  = blk * chunk;
    const int rend  = min(N, rbeg + chunk);
    float acc = 0.0f;
    for (int r = rbeg; r < rend; r++)
        acc += X[(size_t)r * HDIM + t];
    part[blk * HDIM + t] = acc;
}

// Final head: out[c] = head_b[c] + (mean vector) @ head_w.
__global__ __launch_bounds__(256)
void head_kernel(const float* __restrict__ part, const float* __restrict__ hw,
                 const float* __restrict__ hb, float* __restrict__ out, int N)
{
    __shared__ float s[HDIM];
    int t = threadIdx.x;
    float a = 0.0f;
    for (int p = 0; p < 256; p++) a += part[p * HDIM + t];
    s[t] = a * (1.0f / (float)N);
    __syncthreads();
    if (t < 64) {
        float o = hb[t];
        #pragma unroll 8
        for (int h = 0; h < HDIM; h++)
            o = fmaf(s[h], hw[h * 64 + t], o);
        out[t] = o;
    }
}

// ---------------------------------------------------------------------------
// Host side
// ---------------------------------------------------------------------------
static void launch_gemm(const float* A, const float* B, const float* bias, float* C,
                        int M, int K, int Nc, bool post, bool hasbias, bool acc)
{
    dim3 blk(256);
    if (Nc % 128 == 0) {
        dim3 grid((M + BM - 1) / BM, Nc / 128);
        if (post && hasbias)  gemm_tc_kernel<128, true,  true,  false><<<grid, blk>>>(A, B, bias, C, M, K, Nc);
        else if (post)        gemm_tc_kernel<128, true,  false, false><<<grid, blk>>>(A, B, bias, C, M, K, Nc);
        else if (hasbias)     gemm_tc_kernel<128, false, true,  false><<<grid, blk>>>(A, B, bias, C, M, K, Nc);
        else if (acc)         gemm_tc_kernel<128, false, false, true ><<<grid, blk>>>(A, B, bias, C, M, K, Nc);
        else                  gemm_tc_kernel<128, false, false, false><<<grid, blk>>>(A, B, bias, C, M, K, Nc);
    } else {
        dim3 grid((M + BM - 1) / BM, Nc / 64);
        if (post && hasbias)  gemm_tc_kernel<64, true,  true,  false><<<grid, blk>>>(A, B, bias, C, M, K, Nc);
        else if (post)        gemm_tc_kernel<64, true,  false, false><<<grid, blk>>>(A, B, bias, C, M, K, Nc);
        else if (hasbias)     gemm_tc_kernel<64, false, true,  false><<<grid, blk>>>(A, B, bias, C, M, K, Nc);
        else if (acc)         gemm_tc_kernel<64, false, false, true ><<<grid, blk>>>(A, B, bias, C, M, K, Nc);
        else                  gemm_tc_kernel<64, false, false, false><<<grid, blk>>>(A, B, bias, C, M, K, Nc);
    }
}

extern "C" void kernel_launch(void* const* d_in, const int* in_sizes, int n_in,
                              void* d_out, int out_size)
{
    const float* x      = (const float*)d_in[0];
    // d_in[1] = edge_index (unused by reference)
    const float* ff1_w0 = (const float*)d_in[2];
    const float* ff1_b0 = (const float*)d_in[3];
    const float* wA0    = (const float*)d_in[4];
    const float* wB0    = (const float*)d_in[5];
    const float* ff2_w0 = (const float*)d_in[6];
    const float* ff2_b0 = (const float*)d_in[7];
    const float* ff1_w1 = (const float*)d_in[8];
    const float* ff1_b1 = (const float*)d_in[9];
    const float* wA1    = (const float*)d_in[10];
    const float* wB1    = (const float*)d_in[11];
    const float* ff2_w1 = (const float*)d_in[12];
    const float* ff2_b1 = (const float*)d_in[13];
    const float* head_w = (const float*)d_in[14];
    const float* head_b = (const float*)d_in[15];
    float* out = (float*)d_out;

    const int N = in_sizes[0] / HDIM;

    float *pHf, *pG, *pX, *pWt, *pPart, *pAt, *pMp;
    cudaGetSymbolAddress((void**)&pHf,   g_Hf);
    cudaGetSymbolAddress((void**)&pG,    g_G);
    cudaGetSymbolAddress((void**)&pX,    g_X);
    cudaGetSymbolAddress((void**)&pWt,   g_Wt);
    cudaGetSymbolAddress((void**)&pPart, g_part);
    cudaGetSymbolAddress((void**)&pAt,   g_At);
    cudaGetSymbolAddress((void**)&pMp,   g_mp);

    const int n4 = (N * HDIM) / 4;
    const int geluGrid = (n4 + 255) / 256;

    // ---------------- Block 0 ----------------
    launch_gemm(x,   ff1_w0, ff1_b0, pHf, N, HDIM, HDIM, true,  true,  false); // Hf = gelu(X@W1+b)
    launch_gemm(pHf, wA0,    nullptr, pG, N, HDIM, HDIM, true,  false, false); // G  = gelu(Hf@wA)
    launch_gemm(pG,  wB0,    nullptr, pWt, N, HDIM, MDIM, false, false, false); // Wt = G@wB
    spartial_kernel<<<256, 256>>>(pHf, pWt, pPart, N);
    sfinal_kernel<<<64, 256>>>(pPart, pAt);                                    // At = gelu(S)^T
    gelu_inplace_kernel<<<geluGrid, 256>>>(pHf, n4);                           // Hf := gelu(Hf)
    launch_gemm(pWt, pAt,    nullptr, pG, N, MDIM, HDIM, true,  false, false); // P  = gelu(Wt@At)
    launch_gemm(pG,  ff2_w0, ff2_b0, pX, N, HDIM, HDIM, false, true,  false);  // Xo = P@ff2_top+b
    launch_gemm(pHf, ff2_w0 + HDIM * HDIM, nullptr, pX, N, HDIM, HDIM, false, false, true); // Xo += geluHf@ff2_bot

    // ---------------- Block 1 ----------------
    launch_gemm(pX,  ff1_w1, ff1_b1, pHf, N, HDIM, HDIM, true,  true,  false);
    launch_gemm(pHf, wA1,    nullptr, pG, N, HDIM, HDIM, true,  false, false);
    launch_gemm(pG,  wB1,    nullptr, pWt, N, HDIM, MDIM, false, false, false);
    spartial_kernel<<<256, 256>>>(pHf, pWt, pPart, N);
    sfinal_kernel<<<64, 256>>>(pPart, pAt);
    gelu_inplace_kernel<<<geluGrid, 256>>>(pHf, n4);
    launch_gemm(pWt, pAt,    nullptr, pG, N, MDIM, HDIM, true,  false, false);
    launch_gemm(pG,  ff2_w1, ff2_b1, pX, N, HDIM, HDIM, false, true,  false);
    launch_gemm(pHf, ff2_w1 + HDIM * HDIM, nullptr, pX, N, HDIM, HDIM, false, false, true);

    // ---------------- Mean + head ----------------
    meanpart_kernel<<<256, 256>>>(pX, pMp, N);
    head_kernel<<<1, 256>>>(pMp, head_w, head_b, out, N);
}

// round 4
// speedup vs baseline: 2.4382x; 2.4148x over previous
#include <cuda_runtime.h>
#include <cuda_bf16.h>
#include <cstdint>
#include <cstddef>

// ---------------------------------------------------------------------------
// GHM — tcgen05 pipeline (sm_103a pass) with plain-CUDA fallback (compute_103
// pass, which the harness also builds and where tcgen05 is illegal).
// ---------------------------------------------------------------------------

#if defined(__CUDA_ARCH_FEAT_SM103_ALL) || defined(__CUDA_ARCH_FEAT_SM100_ALL)
#define TC05_OK 1
#else
#define TC05_OK 0
#endif

#define NMAX 200000
#define HDIM 256
#define MDIM 64

__device__ float g_Hf [(size_t)NMAX * HDIM];
__device__ float g_G  [(size_t)NMAX * HDIM];   // also reused as P
__device__ float g_X  [(size_t)NMAX * HDIM];
__device__ float g_Wt [(size_t)NMAX * MDIM];
__device__ float g_part[256 * HDIM * MDIM];
__device__ float g_mp [256 * HDIM];
#define W_FF1 0
#define W_WA  65536
#define W_WB  131072
#define W_FF2 147456
#define W_BLK 278528
__device__ __align__(16) __nv_bfloat16 g_wh[2 * W_BLK];
__device__ __align__(16) __nv_bfloat16 g_wl[2 * W_BLK];
__device__ __align__(16) __nv_bfloat16 g_sgh[HDIM * MDIM];
__device__ __align__(16) __nv_bfloat16 g_sgl[HDIM * MDIM];

__device__ __forceinline__ float gelu_f(float x) {
    return 0.5f * x * (1.0f + erff(x * 0.70710678118654752440f));
}
__device__ __forceinline__ uint32_t packbf(float lo, float hi) {
    uint32_t r;
    asm("cvt.rn.bf16x2.f32 %0, %1, %2;" : "=r"(r) : "f"(hi), "f"(lo));
    return r;
}

#if TC05_OK
// ---------------- tcgen05 helpers (verified example fragments) --------------
__device__ __forceinline__ uint32_t elect_one_pred() {
    uint32_t pred;
    asm volatile("{\n\t.reg .pred p;\n\telect.sync _|p, 0xFFFFFFFF;\n\t"
                 "selp.b32 %0, 1, 0, p;\n\t}" : "=r"(pred));
    return pred;
}
__device__ __forceinline__ uint32_t smem_to_u32(const void* p) {
    uint32_t a;
    asm("{ .reg .u64 t; cvta.to.shared.u64 t, %1; cvt.u32.u64 %0, t; }"
        : "=r"(a) : "l"(p));
    return a;
}
#define TCGEN05_ALLOC(sa, n) \
    asm volatile("tcgen05.alloc.cta_group::1.sync.aligned.shared::cta.b32 [%0], %1;" \
                 :: "r"((uint32_t)(sa)), "r"((uint32_t)(n)) : "memory")
#define TCGEN05_DEALLOC(ta, n) \
    asm volatile("tcgen05.dealloc.cta_group::1.sync.aligned.b32 %0, %1;" \
                 :: "r"(ta), "r"((uint32_t)(n)))
#define TCGEN05_COMMIT(mb) \
    asm volatile("tcgen05.commit.cta_group::1.mbarrier::arrive::one.shared::cluster.b64 [%0];" \
                 :: "r"((uint32_t)(mb)) : "memory")
#define TCGEN05_WAIT_LD()  asm volatile("tcgen05.wait::ld.sync.aligned;" ::: "memory")
#define TCGEN05_FENCE_AFTER() asm volatile("tcgen05.fence::after_thread_sync;" ::: "memory")
#define FENCE_ASYNC() asm volatile("fence.proxy.async.shared::cta;" ::: "memory")
#define MBARRIER_INIT(mb, c) \
    asm volatile("mbarrier.init.shared.b64 [%0], %1;" :: "r"((uint32_t)(mb)), "r"((uint32_t)(c)) : "memory")
#define MBARRIER_WAIT_PARITY(mb, ph) do { \
    uint32_t _m = (uint32_t)(mb), _p = (uint32_t)(ph), _d; \
    asm volatile("{\n\t.reg .pred p;\n\t" \
        "mbarrier.try_wait.parity.acquire.cta.shared::cta.b64 p, [%1], %2;\n\t" \
        "selp.b32 %0, 1, 0, p;\n\t}" : "=r"(_d) : "r"(_m), "r"(_p) : "memory"); \
    if (!_d) { \
        asm volatile("{\n\t.reg .pred P1;\n\tWL_%=: \n\t" \
            "mbarrier.try_wait.parity.acquire.cta.shared::cta.b64 P1, [%0], %1, 0x989680;\n\t" \
            "@P1 bra.uni WD_%=;\n\tbra.uni WL_%=;\n\tWD_%=: \n\t}" \
            :: "r"(_m), "r"(_p) : "memory"); \
    } } while (0)
#define TCGEN05_LD_X32(r, ta) \
    asm volatile("tcgen05.ld.sync.aligned.32x32b.x32.b32 " \
        "{%0,%1,%2,%3,%4,%5,%6,%7,%8,%9,%10,%11,%12,%13,%14,%15," \
        "%16,%17,%18,%19,%20,%21,%22,%23,%24,%25,%26,%27,%28,%29,%30,%31}, [%32];" \
        : "=r"((r)[0]),"=r"((r)[1]),"=r"((r)[2]),"=r"((r)[3]),"=r"((r)[4]),"=r"((r)[5]), \
          "=r"((r)[6]),"=r"((r)[7]),"=r"((r)[8]),"=r"((r)[9]),"=r"((r)[10]),"=r"((r)[11]), \
          "=r"((r)[12]),"=r"((r)[13]),"=r"((r)[14]),"=r"((r)[15]),"=r"((r)[16]),"=r"((r)[17]), \
          "=r"((r)[18]),"=r"((r)[19]),"=r"((r)[20]),"=r"((r)[21]),"=r"((r)[22]),"=r"((r)[23]), \
          "=r"((r)[24]),"=r"((r)[25]),"=r"((r)[26]),"=r"((r)[27]),"=r"((r)[28]),"=r"((r)[29]), \
          "=r"((r)[30]),"=r"((r)[31]) : "r"(ta))

static constexpr uint64_t SMEM_DESC_BASE_SW128 =
    (uint64_t(2) << 61) | (uint64_t(1) << 46) | (uint64_t(64) << 32) | (uint64_t(1) << 16);
#define MAKE_SMEM_DESC(a) (SMEM_DESC_BASE_SW128 | ((uint64_t)((a) >> 4) & 0x3FFF))

__device__ __forceinline__ void mma_f16_ss(uint32_t d, uint64_t ad, uint64_t bd,
                                           uint32_t idesc, uint32_t en) {
    asm volatile("{\n\t.reg .pred p;\n\tsetp.ne.u32 p, %5, 0;\n\t"
        "tcgen05.mma.cta_group::1.kind::f16 [%0], %1, %2, %3, {%4,%4,%4,%4}, p;\n\t}"
        :: "r"(d), "l"(ad), "l"(bd), "r"(idesc), "r"(0u), "r"(en) : "memory");
}
#endif // TC05_OK

#define SWZ(b) ((b) ^ (((b) >> 3) & 0x70))

// ---------------------------------------------------------------------------
// GEMM: C(M,Nc) = op(A@B [+bias]); A fp32 row-major; B pre-split bf16 [n][k].
// TWO_A: k<K1 from A (stride K1), k>=K1 from A2 (stride K-K1, gelu'd on load).
// sm_103a: tcgen05 SS bf16, 3-product split-bf16 for ~fp32 accuracy.
// fallback: naive FFMA (correct, slow — only used if non-a cubin is loaded).
// ---------------------------------------------------------------------------
template<bool GELU_OUT, bool HAS_BIAS, bool TWO_A, bool GELU_A2>
__global__ __launch_bounds__(256)
void gemm05_kernel(const float* __restrict__ A, const float* __restrict__ A2,
                   const __nv_bfloat16* __restrict__ Bh, const __nv_bfloat16* __restrict__ Bl,
                   const float* __restrict__ bias, float* __restrict__ C,
                   int M, int K, int K1, int Nc)
{
#if TC05_OK
    extern __shared__ __align__(1024) char sm[];
    const int SM_TPTR = 0, SM_MBAR = 8;
    const int aOff = 1024, alOff = aOff + 16384, bhOff = alOff + 16384;
    const int blOff = bhOff + Nc * 128;

    const int t    = threadIdx.x;
    const int w    = t >> 5;
    const int lane = t & 31;
    const int row0 = blockIdx.x * 128;
    const uint32_t sb = smem_to_u32(sm);

    if (w == 0) TCGEN05_ALLOC(sb + SM_TPTR, 256);
    if (t == 0) MBARRIER_INIT(sb + SM_MBAR, 1);
    __syncthreads();
    uint32_t tmem;
    asm volatile("ld.shared.b32 %0, [%1];" : "=r"(tmem) : "r"(sb + SM_TPTR));

    const uint32_t idesc = (1u << 4) | (1u << 7) | (1u << 10)
                         | ((uint32_t)(Nc / 8) << 17) | (8u << 24);
    const uint64_t adh = MAKE_SMEM_DESC(sb + aOff);
    const uint64_t adl = MAKE_SMEM_DESC(sb + alOff);
    const uint64_t bdh = MAKE_SMEM_DESC(sb + bhOff);
    const uint64_t bdl = MAKE_SMEM_DESC(sb + blOff);

    const int nch = K / 64;
    for (int c = 0; c < nch; ++c) {
        const int kc0 = c * 64;
        const bool useA2 = TWO_A && (kc0 >= K1);
        const float* Asrc = useA2 ? A2 : A;
        const int koff    = useA2 ? (kc0 - K1) : kc0;
        const int strideA = TWO_A ? (useA2 ? (K - K1) : K1) : K;

        // A chunk: 128x64 fp32 -> split bf16 h/l, SW128.
        #pragma unroll
        for (int i = 0; i < 8; i++) {
            int fid = t + i * 256;
            int r = fid >> 4, c16 = fid & 15;
            int gr = row0 + r;
            float4 v = make_float4(0.f, 0.f, 0.f, 0.f);
            if (gr < M)
                v = *reinterpret_cast<const float4*>(&Asrc[(size_t)gr * strideA + koff + c16 * 4]);
            if (GELU_A2 && useA2) {
                v.x = gelu_f(v.x); v.y = gelu_f(v.y); v.z = gelu_f(v.z); v.w = gelu_f(v.w);
            }
            uint32_t h0 = packbf(v.x, v.y), h1 = packbf(v.z, v.w);
            float fx = __uint_as_float(h0 << 16),  fy = __uint_as_float(h0 & 0xffff0000u);
            float fz = __uint_as_float(h1 << 16),  fw = __uint_as_float(h1 & 0xffff0000u);
            uint32_t l0 = packbf(v.x - fx, v.y - fy), l1 = packbf(v.z - fz, v.w - fw);
            int swo = SWZ(r * 128 + c16 * 8);
            *reinterpret_cast<uint2*>(sm + aOff  + swo) = make_uint2(h0, h1);
            *reinterpret_cast<uint2*>(sm + alOff + swo) = make_uint2(l0, l1);
        }
        // B chunk: Nc x 64 bf16 h/l, SW128.
        for (int fid = t; fid < Nc * 8; fid += 256) {
            int n = fid >> 3, c8 = fid & 7;
            size_t src = (size_t)n * K + kc0 + c8 * 8;
            uint4 vh = *reinterpret_cast<const uint4*>(&Bh[src]);
            uint4 vl = *reinterpret_cast<const uint4*>(&Bl[src]);
            int swo = SWZ(n * 128 + c8 * 16);
            *reinterpret_cast<uint4*>(sm + bhOff + swo) = vh;
            *reinterpret_cast<uint4*>(sm + blOff + swo) = vl;
        }
        FENCE_ASYNC();
        __syncthreads();

        if (t < 32) {
            if (elect_one_pred()) {
                #pragma unroll
                for (int ks = 0; ks < 4; ks++) {
                    uint64_t off = (uint64_t)(ks * 2);
                    uint32_t en0 = (c == 0 && ks == 0) ? 0u : 1u;
                    mma_f16_ss(tmem, adh + off, bdh + off, idesc, en0);
                    mma_f16_ss(tmem, adh + off, bdl + off, idesc, 1u);
                    mma_f16_ss(tmem, adl + off, bdh + off, idesc, 1u);
                }
                TCGEN05_COMMIT(sb + SM_MBAR);
            }
        }
        MBARRIER_WAIT_PARITY(sb + SM_MBAR, c & 1);
        __syncthreads();
    }

    TCGEN05_FENCE_AFTER();
    const int row = row0 + (w & 3) * 32 + lane;
    for (int j = (w >> 2); j < Nc / 32; j += 2) {
        uint32_t dr[32];
        TCGEN05_LD_X32(dr, tmem + j * 32);
        TCGEN05_WAIT_LD();
        if (row < M) {
            #pragma unroll
            for (int c4 = 0; c4 < 8; c4++) {
                float4 v; float* pv = &v.x;
                #pragma unroll
                for (int q = 0; q < 4; q++) {
                    float f = __uint_as_float(dr[c4 * 4 + q]);
                    if (HAS_BIAS) f += bias[j * 32 + c4 * 4 + q];
                    if (GELU_OUT) f = gelu_f(f);
                    pv[q] = f;
                }
                *reinterpret_cast<float4*>(&C[(size_t)row * Nc + j * 32 + c4 * 4]) = v;
            }
        }
    }
    __syncthreads();
    if (w == 0) TCGEN05_DEALLOC(tmem, 256);
#else
    // -------- correct fallback (no tcgen05) --------
    const int t    = threadIdx.x;
    const int row0 = blockIdx.x * 128;
    for (int idx = t; idx < 128 * Nc; idx += 256) {
        int r = idx / Nc, n = idx % Nc;
        int gr = row0 + r;
        if (gr >= M) continue;
        float acc = 0.0f;
        const __nv_bfloat16* bh = Bh + (size_t)n * K;
        const __nv_bfloat16* bl = Bl + (size_t)n * K;
        for (int k = 0; k < K; k++) {
            bool u2 = TWO_A && (k >= K1);
            float a = u2 ? A2[(size_t)gr * (K - K1) + (k - K1)]
                         : A[(size_t)gr * (TWO_A ? K1 : K) + k];
            if (GELU_A2 && u2) a = gelu_f(a);
            float b = __bfloat162float(bh[k]) + __bfloat162float(bl[k]);
            acc = fmaf(a, b, acc);
        }
        if (HAS_BIAS) acc += bias[n];
        if (GELU_OUT) acc = gelu_f(acc);
        C[(size_t)gr * Nc + n] = acc;
    }
#endif
}

// ---------------------------------------------------------------------------
__global__ void transsplit_kernel(const float* __restrict__ src,
                                  __nv_bfloat16* __restrict__ dh,
                                  __nv_bfloat16* __restrict__ dl, int K, int Nc)
{
    int idx = blockIdx.x * 256 + threadIdx.x;
    if (idx < K * Nc) {
        int n = idx / K, k = idx % K;
        float v = src[(size_t)k * Nc + n];
        __nv_bfloat16 h = __float2bfloat16_rn(v);
        dh[idx] = h;
        dl[idx] = __float2bfloat16_rn(v - __bfloat162float(h));
    }
}

__global__ __launch_bounds__(512)
void spartial_kernel(const float* __restrict__ Hf, const float* __restrict__ Wt,
                     float* __restrict__ part, int N)
{
    __shared__ float ws[16 * MDIM];
    const int t = threadIdx.x;
    const int hq = t & 127, mq = t >> 7;
    const int blk = blockIdx.x;
    const int chunk = (N + 255) / 256;
    const int rbeg = blk * chunk;
    const int rend = min(N, rbeg + chunk);

    float acc[2][16];
    #pragma unroll
    for (int j = 0; j < 2; j++)
        #pragma unroll
        for (int i = 0; i < 16; i++) acc[j][i] = 0.0f;

    for (int r = rbeg; r < rend; r += 16) {
        int nr = min(16, rend - r);
        __syncthreads();
        for (int i = t; i < nr * MDIM; i += 512)
            ws[i] = Wt[(size_t)r * MDIM + i];
        __syncthreads();
        int rr = 0;
        for (; rr + 2 <= nr; rr += 2) {
            float2 ha = *reinterpret_cast<const float2*>(&Hf[(size_t)(r + rr) * HDIM + hq * 2]);
            float2 hb = *reinterpret_cast<const float2*>(&Hf[(size_t)(r + rr + 1) * HDIM + hq * 2]);
            #pragma unroll
            for (int i = 0; i < 16; i++) {
                float wa = ws[rr * MDIM + mq * 16 + i];
                float wb = ws[(rr + 1) * MDIM + mq * 16 + i];
                acc[0][i] = fmaf(ha.x, wa, acc[0][i]);
                acc[1][i] = fmaf(ha.y, wa, acc[1][i]);
                acc[0][i] = fmaf(hb.x, wb, acc[0][i]);
                acc[1][i] = fmaf(hb.y, wb, acc[1][i]);
            }
        }
        for (; rr < nr; rr++) {
            float2 ha = *reinterpret_cast<const float2*>(&Hf[(size_t)(r + rr) * HDIM + hq * 2]);
            #pragma unroll
            for (int i = 0; i < 16; i++) {
                float wa = ws[rr * MDIM + mq * 16 + i];
                acc[0][i] = fmaf(ha.x, wa, acc[0][i]);
                acc[1][i] = fmaf(ha.y, wa, acc[1][i]);
            }
        }
    }
    #pragma unroll
    for (int j = 0; j < 2; j++) {
        float* p = part + (size_t)blk * HDIM * MDIM + (size_t)(hq * 2 + j) * MDIM + mq * 16;
        #pragma unroll
        for (int i4 = 0; i4 < 4; i4++)
            *reinterpret_cast<float4*>(&p[i4 * 4]) =
                make_float4(acc[j][i4 * 4], acc[j][i4 * 4 + 1], acc[j][i4 * 4 + 2], acc[j][i4 * 4 + 3]);
    }
}

__global__ __launch_bounds__(256)
void sfinal_kernel(const float* __restrict__ part,
                   __nv_bfloat16* __restrict__ sgh, __nv_bfloat16* __restrict__ sgl)
{
    int idx = blockIdx.x * 256 + threadIdx.x;  // h*64+m
    float s = 0.0f;
    for (int p = 0; p < 256; p++)
        s += part[(size_t)p * HDIM * MDIM + idx];
    float g = gelu_f(s);
    __nv_bfloat16 h = __float2bfloat16_rn(g);
    sgh[idx] = h;
    sgl[idx] = __float2bfloat16_rn(g - __bfloat162float(h));
}

__global__ __launch_bounds__(256)
void meanpart_kernel(const float* __restrict__ X, float* __restrict__ part, int N)
{
    const int t = threadIdx.x, blk = blockIdx.x;
    const int chunk = (N + 255) / 256;
    const int rbeg = blk * chunk;
    const int rend = min(N, rbeg + chunk);
    float acc = 0.0f;
    for (int r = rbeg; r < rend; r++)
        acc += X[(size_t)r * HDIM + t];
    part[blk * HDIM + t] = acc;
}

__global__ __launch_bounds__(256)
void head_kernel(const float* __restrict__ part, const float* __restrict__ hw,
                 const float* __restrict__ hb, float* __restrict__ out, int N)
{
    __shared__ float s[HDIM];
    int t = threadIdx.x;
    float a = 0.0f;
    for (int p = 0; p < 256; p++) a += part[p * HDIM + t];
    s[t] = a * (1.0f / (float)N);
    __syncthreads();
    if (t < 64) {
        float o = hb[t];
        #pragma unroll 8
        for (int h = 0; h < HDIM; h++)
            o = fmaf(s[h], hw[h * 64 + t], o);
        out[t] = o;
    }
}

// ---------------------------------------------------------------------------
// Host
// ---------------------------------------------------------------------------
#define GSMEM(Nc) (33792 + (Nc) * 256)

template<bool GO, bool HB, bool TA, bool GA>
static void launch_g05(const float* A, const float* A2,
                       const __nv_bfloat16* Bh, const __nv_bfloat16* Bl,
                       const float* bias, float* C, int M, int K, int K1, int Nc)
{
    cudaFuncSetAttribute(gemm05_kernel<GO, HB, TA, GA>,
                         cudaFuncAttributeMaxDynamicSharedMemorySize, GSMEM(256));
    gemm05_kernel<GO, HB, TA, GA><<<(M + 127) / 128, 256, GSMEM(Nc)>>>(
        A, A2, Bh, Bl, bias, C, M, K, K1, Nc);
}

extern "C" void kernel_launch(void* const* d_in, const int* in_sizes, int n_in,
                              void* d_out, int out_size)
{
    const float* x      = (const float*)d_in[0];
    const float* ff1_w0 = (const float*)d_in[2];
    const float* ff1_b0 = (const float*)d_in[3];
    const float* wA0    = (const float*)d_in[4];
    const float* wB0    = (const float*)d_in[5];
    const float* ff2_w0 = (const float*)d_in[6];
    const float* ff2_b0 = (const float*)d_in[7];
    const float* ff1_w1 = (const float*)d_in[8];
    const float* ff1_b1 = (const float*)d_in[9];
    const float* wA1    = (const float*)d_in[10];
    const float* wB1    = (const float*)d_in[11];
    const float* ff2_w1 = (const float*)d_in[12];
    const float* ff2_b1 = (const float*)d_in[13];
    const float* head_w = (const float*)d_in[14];
    const float* head_b = (const float*)d_in[15];
    float* out = (float*)d_out;

    const int N = in_sizes[0] / HDIM;

    float *pHf, *pG, *pX, *pWt, *pPart, *pMp;
    __nv_bfloat16 *pWh, *pWl, *pSgh, *pSgl;
    cudaGetSymbolAddress((void**)&pHf,   g_Hf);
    cudaGetSymbolAddress((void**)&pG,    g_G);
    cudaGetSymbolAddress((void**)&pX,    g_X);
    cudaGetSymbolAddress((void**)&pWt,   g_Wt);
    cudaGetSymbolAddress((void**)&pPart, g_part);
    cudaGetSymbolAddress((void**)&pMp,   g_mp);
    cudaGetSymbolAddress((void**)&pWh,   g_wh);
    cudaGetSymbolAddress((void**)&pWl,   g_wl);
    cudaGetSymbolAddress((void**)&pSgh,  g_sgh);
    cudaGetSymbolAddress((void**)&pSgl,  g_sgl);

    struct { const float* src; int off, K, Nc; } wp[8] = {
        {ff1_w0, W_FF1,          256, 256}, {wA0, W_WA,          256, 256},
        {wB0,    W_WB,           256,  64}, {ff2_w0, W_FF2,      512, 256},
        {ff1_w1, W_BLK + W_FF1,  256, 256}, {wA1, W_BLK + W_WA,  256, 256},
        {wB1,    W_BLK + W_WB,   256,  64}, {ff2_w1, W_BLK + W_FF2, 512, 256},
    };
    for (int i = 0; i < 8; i++) {
        int n = wp[i].K * wp[i].Nc;
        transsplit_kernel<<<(n + 255) / 256, 256>>>(wp[i].src, pWh + wp[i].off,
                                                    pWl + wp[i].off, wp[i].K, wp[i].Nc);
    }

    const float* Xin = x;
    const float* ff1b[2] = {ff1_b0, ff1_b1};
    const float* ff2b[2] = {ff2_b0, ff2_b1};
    for (int b = 0; b < 2; b++) {
        int wo = b * W_BLK;
        launch_g05<true, true, false, false>(Xin, nullptr, pWh + wo + W_FF1, pWl + wo + W_FF1,
                                             ff1b[b], pHf, N, 256, 0, 256);
        launch_g05<true, false, false, false>(pHf, nullptr, pWh + wo + W_WA, pWl + wo + W_WA,
                                              nullptr, pG, N, 256, 0, 256);
        launch_g05<false, false, false, false>(pG, nullptr, pWh + wo + W_WB, pWl + wo + W_WB,
                                               nullptr, pWt, N, 256, 0, 64);
        spartial_kernel<<<256, 512>>>(pHf, pWt, pPart, N);
        sfinal_kernel<<<64, 256>>>(pPart, pSgh, pSgl);
        launch_g05<true, false, false, false>(pWt, nullptr, pSgh, pSgl,
                                              nullptr, pG, N, 64, 0, 256);
        launch_g05<false, true, true, true>(pG, pHf, pWh + wo + W_FF2, pWl + wo + W_FF2,
                                            ff2b[b], pX, N, 512, 256, 256);
        Xin = pX;
    }

    meanpart_kernel<<<256, 256>>>(pX, pMp, N);
    head_kernel<<<1, 256>>>(pMp, head_w, head_b, out, N);
}

// round 5
// speedup vs baseline: 2.6402x; 1.0828x over previous
#include <cuda_runtime.h>
#include <cuda_bf16.h>
#include <cstdint>
#include <cstddef>

// ---------------------------------------------------------------------------
// GHM — tcgen05 pipeline, double-buffered, fused G->Wt stage.
// sm_103a pass uses tcgen05; compute_103 pass gets a slow-but-correct fallback.
// ---------------------------------------------------------------------------

#if defined(__CUDA_ARCH_FEAT_SM103_ALL) || defined(__CUDA_ARCH_FEAT_SM100_ALL)
#define TC05_OK 1
#else
#define TC05_OK 0
#endif

#define NMAX 200000
#define HDIM 256
#define MDIM 64
#define NTH  512
#define SPBLK 512

__device__ float g_Hf [(size_t)NMAX * HDIM];
__device__ float g_G  [(size_t)NMAX * HDIM];   // P buffer
__device__ float g_X  [(size_t)NMAX * HDIM];
__device__ float g_Wt [(size_t)NMAX * MDIM];
__device__ float g_part[(size_t)SPBLK * HDIM * MDIM];
__device__ float g_mp [256 * HDIM];
#define W_FF1 0
#define W_WA  65536
#define W_WB  131072
#define W_FF2 147456
#define W_BLK 278528
__device__ __align__(16) __nv_bfloat16 g_wh[2 * W_BLK];
__device__ __align__(16) __nv_bfloat16 g_wl[2 * W_BLK];
__device__ __align__(16) __nv_bfloat16 g_sgh[HDIM * MDIM];
__device__ __align__(16) __nv_bfloat16 g_sgl[HDIM * MDIM];

__device__ __forceinline__ float gelu_f(float x) {
    return 0.5f * x * (1.0f + erff(x * 0.70710678118654752440f));
}
// bf16x2 with lo in low half
__device__ __forceinline__ uint32_t packbf(float lo, float hi) {
    uint32_t r;
    asm("cvt.rn.bf16x2.f32 %0, %1, %2;" : "=r"(r) : "f"(hi), "f"(lo));
    return r;
}

#if TC05_OK
__device__ __forceinline__ uint32_t elect_one_pred() {
    uint32_t pred;
    asm volatile("{\n\t.reg .pred p;\n\telect.sync _|p, 0xFFFFFFFF;\n\t"
                 "selp.b32 %0, 1, 0, p;\n\t}" : "=r"(pred));
    return pred;
}
__device__ __forceinline__ uint32_t smem_to_u32(const void* p) {
    uint32_t a;
    asm("{ .reg .u64 t; cvta.to.shared.u64 t, %1; cvt.u32.u64 %0, t; }"
        : "=r"(a) : "l"(p));
    return a;
}
#define TCGEN05_ALLOC(sa, n) \
    asm volatile("tcgen05.alloc.cta_group::1.sync.aligned.shared::cta.b32 [%0], %1;" \
                 :: "r"((uint32_t)(sa)), "r"((uint32_t)(n)) : "memory")
#define TCGEN05_DEALLOC(ta, n) \
    asm volatile("tcgen05.dealloc.cta_group::1.sync.aligned.b32 %0, %1;" \
                 :: "r"(ta), "r"((uint32_t)(n)))
#define TCGEN05_COMMIT(mb) \
    asm volatile("tcgen05.commit.cta_group::1.mbarrier::arrive::one.shared::cluster.b64 [%0];" \
                 :: "r"((uint32_t)(mb)) : "memory")
#define TCGEN05_WAIT_LD()  asm volatile("tcgen05.wait::ld.sync.aligned;" ::: "memory")
#define TCGEN05_FENCE_AFTER() asm volatile("tcgen05.fence::after_thread_sync;" ::: "memory")
#define FENCE_ASYNC() asm volatile("fence.proxy.async.shared::cta;" ::: "memory")
#define MBARRIER_INIT(mb, c) \
    asm volatile("mbarrier.init.shared.b64 [%0], %1;" :: "r"((uint32_t)(mb)), "r"((uint32_t)(c)) : "memory")
#define MBARRIER_WAIT_PARITY(mb, ph) do { \
    uint32_t _m = (uint32_t)(mb), _p = (uint32_t)(ph), _d; \
    asm volatile("{\n\t.reg .pred p;\n\t" \
        "mbarrier.try_wait.parity.acquire.cta.shared::cta.b64 p, [%1], %2;\n\t" \
        "selp.b32 %0, 1, 0, p;\n\t}" : "=r"(_d) : "r"(_m), "r"(_p) : "memory"); \
    if (!_d) { \
        asm volatile("{\n\t.reg .pred P1;\n\tWL_%=: \n\t" \
            "mbarrier.try_wait.parity.acquire.cta.shared::cta.b64 P1, [%0], %1, 0x989680;\n\t" \
            "@P1 bra.uni WD_%=;\n\tbra.uni WL_%=;\n\tWD_%=: \n\t}" \
            :: "r"(_m), "r"(_p) : "memory"); \
    } } while (0)
#define TCGEN05_LD_X32(r, ta) \
    asm volatile("tcgen05.ld.sync.aligned.32x32b.x32.b32 " \
        "{%0,%1,%2,%3,%4,%5,%6,%7,%8,%9,%10,%11,%12,%13,%14,%15," \
        "%16,%17,%18,%19,%20,%21,%22,%23,%24,%25,%26,%27,%28,%29,%30,%31}, [%32];" \
        : "=r"((r)[0]),"=r"((r)[1]),"=r"((r)[2]),"=r"((r)[3]),"=r"((r)[4]),"=r"((r)[5]), \
          "=r"((r)[6]),"=r"((r)[7]),"=r"((r)[8]),"=r"((r)[9]),"=r"((r)[10]),"=r"((r)[11]), \
          "=r"((r)[12]),"=r"((r)[13]),"=r"((r)[14]),"=r"((r)[15]),"=r"((r)[16]),"=r"((r)[17]), \
          "=r"((r)[18]),"=r"((r)[19]),"=r"((r)[20]),"=r"((r)[21]),"=r"((r)[22]),"=r"((r)[23]), \
          "=r"((r)[24]),"=r"((r)[25]),"=r"((r)[26]),"=r"((r)[27]),"=r"((r)[28]),"=r"((r)[29]), \
          "=r"((r)[30]),"=r"((r)[31]) : "r"(ta))

static constexpr uint64_t SMEM_DESC_BASE_SW128 =
    (uint64_t(2) << 61) | (uint64_t(1) << 46) | (uint64_t(64) << 32) | (uint64_t(1) << 16);
#define MAKE_SMEM_DESC(a) (SMEM_DESC_BASE_SW128 | ((uint64_t)((a) >> 4) & 0x3FFF))

__device__ __forceinline__ void mma_f16_ss(uint32_t d, uint64_t ad, uint64_t bd,
                                           uint32_t idesc, uint32_t en) {
    asm volatile("{\n\t.reg .pred p;\n\tsetp.ne.u32 p, %5, 0;\n\t"
        "tcgen05.mma.cta_group::1.kind::f16 [%0], %1, %2, %3, {%4,%4,%4,%4}, p;\n\t}"
        :: "r"(d), "l"(ad), "l"(bd), "r"(idesc), "r"(0u), "r"(en) : "memory");
}
#endif // TC05_OK

#define SWZ(b) ((b) ^ (((b) >> 3) & 0x70))
// smem map (bytes): [0] tmem ptr, [8],[16] mbar0/1
// A buffers: 1024 + b*32768 (h @+0, l @+16384)
// B buffers: 66560 + b*(Nc*256) (h @+0, l @+Nc*128)
#define AOFF(b)  (1024 + (b) * 32768)
#define BBASE    66560

// ---------------------------------------------------------------------------
// Plain tcgen05 GEMM, double-buffered. C = op(A@B [+bias]).
// A fp32 row-major (split to bf16 h/l on load); B pre-split bf16 [n][k].
// TWO_A: k<K1 from A (stride K1), k>=K1 from A2 (stride K-K1, gelu'd on load).
// ---------------------------------------------------------------------------
template<bool GELU_OUT, bool HAS_BIAS, bool TWO_A, bool GELU_A2>
__global__ __launch_bounds__(NTH)
void gemm05_kernel(const float* __restrict__ A, const float* __restrict__ A2,
                   const __nv_bfloat16* __restrict__ Bh, const __nv_bfloat16* __restrict__ Bl,
                   const float* __restrict__ bias, float* __restrict__ C,
                   int M, int K, int K1, int Nc)
{
#if TC05_OK
    extern __shared__ __align__(1024) char sm[];
    const int t = threadIdx.x, w = t >> 5, lane = t & 31;
    const int row0 = blockIdx.x * 128;
    const uint32_t sb = smem_to_u32(sm);

    if (w == 0) TCGEN05_ALLOC(sb + 0, 256);
    if (t == 0) { MBARRIER_INIT(sb + 8, 1); MBARRIER_INIT(sb + 16, 1); }
    __syncthreads();
    uint32_t tmem;
    asm volatile("ld.shared.b32 %0, [%1];" : "=r"(tmem) : "r"(sb + 0));

    const uint32_t idesc = (1u << 4) | (1u << 7) | (1u << 10)
                         | ((uint32_t)(Nc / 8) << 17) | (8u << 24);
    const int bBytes = Nc * 256;
    const int nch = K / 64;

    for (int c = 0; c < nch; ++c) {
        const int b  = c & 1;
        const int kb = c >> 1;
        if (kb >= 1) MBARRIER_WAIT_PARITY(sb + 8 + b * 8, (kb - 1) & 1);

        const int kc0 = c * 64;
        const bool useA2 = TWO_A && (kc0 >= K1);
        const float* Asrc = useA2 ? A2 : A;
        const int koff    = useA2 ? (kc0 - K1) : kc0;
        const int strideA = TWO_A ? (useA2 ? (K - K1) : K1) : K;
        char* aB = sm + AOFF(b);
        char* bB = sm + BBASE + b * bBytes;

        #pragma unroll
        for (int i = 0; i < 4; i++) {
            int fid = t + i * NTH;                  // 0..2047
            int r = fid >> 4, c16 = fid & 15;
            int gr = row0 + r;
            float4 v = make_float4(0.f, 0.f, 0.f, 0.f);
            if (gr < M)
                v = *reinterpret_cast<const float4*>(&Asrc[(size_t)gr * strideA + koff + c16 * 4]);
            if (GELU_A2 && useA2) {
                v.x = gelu_f(v.x); v.y = gelu_f(v.y); v.z = gelu_f(v.z); v.w = gelu_f(v.w);
            }
            uint32_t h0 = packbf(v.x, v.y), h1 = packbf(v.z, v.w);
            float fx = __uint_as_float(h0 << 16),  fy = __uint_as_float(h0 & 0xffff0000u);
            float fz = __uint_as_float(h1 << 16),  fw = __uint_as_float(h1 & 0xffff0000u);
            uint32_t l0 = packbf(v.x - fx, v.y - fy), l1 = packbf(v.z - fz, v.w - fw);
            int swo = SWZ(r * 128 + c16 * 8);
            *reinterpret_cast<uint2*>(aB + swo)         = make_uint2(h0, h1);
            *reinterpret_cast<uint2*>(aB + 16384 + swo) = make_uint2(l0, l1);
        }
        for (int fid = t; fid < Nc * 8; fid += NTH) {
            int n = fid >> 3, c8 = fid & 7;
            size_t src = (size_t)n * K + kc0 + c8 * 8;
            uint4 vh = *reinterpret_cast<const uint4*>(&Bh[src]);
            uint4 vl = *reinterpret_cast<const uint4*>(&Bl[src]);
            int swo = SWZ(n * 128 + c8 * 16);
            *reinterpret_cast<uint4*>(bB + swo)            = vh;
            *reinterpret_cast<uint4*>(bB + Nc * 128 + swo) = vl;
        }
        FENCE_ASYNC();
        __syncthreads();

        if (t < 32) {
            if (elect_one_pred()) {
                const uint64_t adh = MAKE_SMEM_DESC(sb + AOFF(b));
                const uint64_t adl = MAKE_SMEM_DESC(sb + AOFF(b) + 16384);
                const uint64_t bdh = MAKE_SMEM_DESC(sb + BBASE + b * bBytes);
                const uint64_t bdl = MAKE_SMEM_DESC(sb + BBASE + b * bBytes + Nc * 128);
                #pragma unroll
                for (int ks = 0; ks < 4; ks++) {
                    uint64_t off = (uint64_t)(ks * 2);
                    uint32_t en0 = (c == 0 && ks == 0) ? 0u : 1u;
                    mma_f16_ss(tmem, adh + off, bdh + off, idesc, en0);
                    mma_f16_ss(tmem, adh + off, bdl + off, idesc, 1u);
                    mma_f16_ss(tmem, adl + off, bdh + off, idesc, 1u);
                }
                TCGEN05_COMMIT(sb + 8 + b * 8);
            }
        }
    }
    MBARRIER_WAIT_PARITY(sb + 8 + ((nch - 1) & 1) * 8, ((nch - 1) >> 1) & 1);
    TCGEN05_FENCE_AFTER();

    const int row = row0 + (w & 3) * 32 + lane;
    for (int j = (w >> 2); j < Nc / 32; j += 4) {
        uint32_t dr[32];
        TCGEN05_LD_X32(dr, tmem + j * 32);
        TCGEN05_WAIT_LD();
        if (row < M) {
            #pragma unroll
            for (int c4 = 0; c4 < 8; c4++) {
                float4 v; float* pv = &v.x;
                #pragma unroll
                for (int q = 0; q < 4; q++) {
                    float f = __uint_as_float(dr[c4 * 4 + q]);
                    if (HAS_BIAS) f += bias[j * 32 + c4 * 4 + q];
                    if (GELU_OUT) f = gelu_f(f);
                    pv[q] = f;
                }
                *reinterpret_cast<float4*>(&C[(size_t)row * Nc + j * 32 + c4 * 4]) = v;
            }
        }
    }
    __syncthreads();
    if (w == 0) TCGEN05_DEALLOC(tmem, 256);
#else
    const int t = threadIdx.x;
    const int row0 = blockIdx.x * 128;
    for (int idx = t; idx < 128 * Nc; idx += NTH) {
        int r = idx / Nc, n = idx % Nc;
        int gr = row0 + r;
        if (gr >= M) continue;
        float acc = 0.0f;
        const __nv_bfloat16* bh = Bh + (size_t)n * K;
        const __nv_bfloat16* bl = Bl + (size_t)n * K;
        for (int k = 0; k < K; k++) {
            bool u2 = TWO_A && (k >= K1);
            float a = u2 ? A2[(size_t)gr * (K - K1) + (k - K1)]
                         : A[(size_t)gr * (TWO_A ? K1 : K) + k];
            if (GELU_A2 && u2) a = gelu_f(a);
            float bv = __bfloat162float(bh[k]) + __bfloat162float(bl[k]);
            acc = fmaf(a, bv, acc);
        }
        if (HAS_BIAS) acc += bias[n];
        if (GELU_OUT) acc = gelu_f(acc);
        C[(size_t)gr * Nc + n] = acc;
    }
#endif
}

// ---------------------------------------------------------------------------
// Fused: G = gelu(Hf @ wA) kept in SMEM (split-bf16 A tiles), Wt = G @ wB.
// Hf (M,256) fp32; wA split [h][k] 256x256; wB split [n][h] 64x256; Wt (M,64).
// smem: stage1 = A db + B db (197632). stage2 reuse: G @1024 (4 x 32KB),
// wB @132096 (h 4x8KB, then l 4x8KB).
// ---------------------------------------------------------------------------
__global__ __launch_bounds__(NTH)
void gemmGW_kernel(const float* __restrict__ Hf,
                   const __nv_bfloat16* __restrict__ Bh, const __nv_bfloat16* __restrict__ Bl,
                   const __nv_bfloat16* __restrict__ B2h, const __nv_bfloat16* __restrict__ B2l,
                   float* __restrict__ Wt, int M)
{
#if TC05_OK
    extern __shared__ __align__(1024) char sm[];
    const int t = threadIdx.x, w = t >> 5, lane = t & 31;
    const int row0 = blockIdx.x * 128;
    const uint32_t sb = smem_to_u32(sm);

    if (w == 0) TCGEN05_ALLOC(sb + 0, 512);
    if (t == 0) { MBARRIER_INIT(sb + 8, 1); MBARRIER_INIT(sb + 16, 1); }
    __syncthreads();
    uint32_t tmem;
    asm volatile("ld.shared.b32 %0, [%1];" : "=r"(tmem) : "r"(sb + 0));

    const uint32_t idesc1 = (1u << 4) | (1u << 7) | (1u << 10) | (32u << 17) | (8u << 24);
    const uint32_t idesc2 = (1u << 4) | (1u << 7) | (1u << 10) | (8u  << 17) | (8u << 24);

    // ---------- stage 1: G = Hf @ wA into TMEM cols 0..255 ----------
    for (int c = 0; c < 4; ++c) {
        const int b = c & 1, kb = c >> 1;
        if (kb >= 1) MBARRIER_WAIT_PARITY(sb + 8 + b * 8, (kb - 1) & 1);
        const int kc0 = c * 64;
        char* aB = sm + AOFF(b);
        char* bB = sm + BBASE + b * 65536;

        #pragma unroll
        for (int i = 0; i < 4; i++) {
            int fid = t + i * NTH;
            int r = fid >> 4, c16 = fid & 15;
            int gr = row0 + r;
            float4 v = make_float4(0.f, 0.f, 0.f, 0.f);
            if (gr < M)
                v = *reinterpret_cast<const float4*>(&Hf[(size_t)gr * 256 + kc0 + c16 * 4]);
            uint32_t h0 = packbf(v.x, v.y), h1 = packbf(v.z, v.w);
            float fx = __uint_as_float(h0 << 16),  fy = __uint_as_float(h0 & 0xffff0000u);
            float fz = __uint_as_float(h1 << 16),  fw = __uint_as_float(h1 & 0xffff0000u);
            uint32_t l0 = packbf(v.x - fx, v.y - fy), l1 = packbf(v.z - fz, v.w - fw);
            int swo = SWZ(r * 128 + c16 * 8);
            *reinterpret_cast<uint2*>(aB + swo)         = make_uint2(h0, h1);
            *reinterpret_cast<uint2*>(aB + 16384 + swo) = make_uint2(l0, l1);
        }
        for (int fid = t; fid < 2048; fid += NTH) {
            int n = fid >> 3, c8 = fid & 7;
            size_t src = (size_t)n * 256 + kc0 + c8 * 8;
            uint4 vh = *reinterpret_cast<const uint4*>(&Bh[src]);
            uint4 vl = *reinterpret_cast<const uint4*>(&Bl[src]);
            int swo = SWZ(n * 128 + c8 * 16);
            *reinterpret_cast<uint4*>(bB + swo)         = vh;
            *reinterpret_cast<uint4*>(bB + 32768 + swo) = vl;
        }
        FENCE_ASYNC();
        __syncthreads();

        if (t < 32) {
            if (elect_one_pred()) {
                const uint64_t adh = MAKE_SMEM_DESC(sb + AOFF(b));
                const uint64_t adl = MAKE_SMEM_DESC(sb + AOFF(b) + 16384);
                const uint64_t bdh = MAKE_SMEM_DESC(sb + BBASE + b * 65536);
                const uint64_t bdl = MAKE_SMEM_DESC(sb + BBASE + b * 65536 + 32768);
                #pragma unroll
                for (int ks = 0; ks < 4; ks++) {
                    uint64_t off = (uint64_t)(ks * 2);
                    uint32_t en0 = (c == 0 && ks == 0) ? 0u : 1u;
                    mma_f16_ss(tmem, adh + off, bdh + off, idesc1, en0);
                    mma_f16_ss(tmem, adh + off, bdl + off, idesc1, 1u);
                    mma_f16_ss(tmem, adl + off, bdh + off, idesc1, 1u);
                }
                TCGEN05_COMMIT(sb + 8 + b * 8);
            }
        }
    }
    MBARRIER_WAIT_PARITY(sb + 16, 1);   // last commit: chunk 3 -> mbar1 #2
    TCGEN05_FENCE_AFTER();

    // ---------- mid-epilogue: gelu(D1) -> SMEM G (split A tiles) ----------
    {
        const int r = (w & 3) * 32 + lane;     // local row
        for (int j = (w >> 2); j < 8; j += 4) {
            uint32_t dr[32];
            TCGEN05_LD_X32(dr, tmem + j * 32);
            TCGEN05_WAIT_LD();
            char* gh = sm + 1024 + (j >> 1) * 32768;
            char* gl = gh + 16384;
            #pragma unroll
            for (int p = 0; p < 16; p++) {
                float f0 = gelu_f(__uint_as_float(dr[2 * p]));
                float f1 = gelu_f(__uint_as_float(dr[2 * p + 1]));
                uint32_t hh = packbf(f0, f1);
                float fx = __uint_as_float(hh << 16), fy = __uint_as_float(hh & 0xffff0000u);
                uint32_t ll = packbf(f0 - fx, f1 - fy);
                int off = SWZ(r * 128 + (j & 1) * 64 + p * 4);
                *reinterpret_cast<uint32_t*>(gh + off) = hh;
                *reinterpret_cast<uint32_t*>(gl + off) = ll;
            }
        }
        // load wB tiles: 64 rows x 256 k, split into 4 64-k chunk tiles
        for (int fid = t; fid < 2048; fid += NTH) {
            int n = fid >> 5, k8 = fid & 31;
            int k = k8 * 8, ch = k >> 6;
            size_t src = (size_t)n * 256 + k;
            uint4 vh = *reinterpret_cast<const uint4*>(&B2h[src]);
            uint4 vl = *reinterpret_cast<const uint4*>(&B2l[src]);
            int off = SWZ(n * 128 + (k & 63) * 2);
            *reinterpret_cast<uint4*>(sm + 132096 + ch * 8192 + off)         = vh;
            *reinterpret_cast<uint4*>(sm + 132096 + 32768 + ch * 8192 + off) = vl;
        }
    }
    FENCE_ASYNC();
    __syncthreads();

    // ---------- stage 2: Wt = G @ wB into TMEM cols 256..319 ----------
    if (t < 32) {
        if (elect_one_pred()) {
            for (int c2 = 0; c2 < 4; c2++) {
                const uint64_t adh = MAKE_SMEM_DESC(sb + 1024 + c2 * 32768);
                const uint64_t adl = MAKE_SMEM_DESC(sb + 1024 + c2 * 32768 + 16384);
                const uint64_t bdh = MAKE_SMEM_DESC(sb + 132096 + c2 * 8192);
                const uint64_t bdl = MAKE_SMEM_DESC(sb + 132096 + 32768 + c2 * 8192);
                #pragma unroll
                for (int ks = 0; ks < 4; ks++) {
                    uint64_t off = (uint64_t)(ks * 2);
                    uint32_t en0 = (c2 == 0 && ks == 0) ? 0u : 1u;
                    mma_f16_ss(tmem + 256, adh + off, bdh + off, idesc2, en0);
                    mma_f16_ss(tmem + 256, adh + off, bdl + off, idesc2, 1u);
                    mma_f16_ss(tmem + 256, adl + off, bdh + off, idesc2, 1u);
                }
            }
            TCGEN05_COMMIT(sb + 8);        // mbar0 commit #3
        }
    }
    MBARRIER_WAIT_PARITY(sb + 8, 0);
    TCGEN05_FENCE_AFTER();

    // ---------- epilogue 2: Wt fp32 ----------
    {
        const int row = row0 + (w & 3) * 32 + lane;
        int j = w >> 2;
        if (j < 2) {
            uint32_t dr[32];
            TCGEN05_LD_X32(dr, tmem + 256 + j * 32);
            TCGEN05_WAIT_LD();
            if (row < M) {
                #pragma unroll
                for (int c4 = 0; c4 < 8; c4++) {
                    float4 v = make_float4(__uint_as_float(dr[c4 * 4]),
                                           __uint_as_float(dr[c4 * 4 + 1]),
                                           __uint_as_float(dr[c4 * 4 + 2]),
                                           __uint_as_float(dr[c4 * 4 + 3]));
                    *reinterpret_cast<float4*>(&Wt[(size_t)row * 64 + j * 32 + c4 * 4]) = v;
                }
            }
        }
    }
    __syncthreads();
    if (w == 0) TCGEN05_DEALLOC(tmem, 512);
#else
    // fallback: per row, compute G row then Wt row (slow, correctness only)
    __shared__ float hrow[256];
    __shared__ float grow[256];
    const int row0 = blockIdx.x * 128;
    const int t = threadIdx.x;
    for (int r = 0; r < 128; r++) {
        int gr = row0 + r;
        if (gr >= M) break;
        for (int k = t; k < 256; k += NTH) hrow[k] = Hf[(size_t)gr * 256 + k];
        __syncthreads();
        for (int h = t; h < 256; h += NTH) {
            float acc = 0.0f;
            for (int k = 0; k < 256; k++)
                acc = fmaf(hrow[k], __bfloat162float(Bh[(size_t)h * 256 + k]) +
                                    __bfloat162float(Bl[(size_t)h * 256 + k]), acc);
            grow[h] = gelu_f(acc);
        }
        __syncthreads();
        for (int n = t; n < 64; n += NTH) {
            float acc = 0.0f;
            for (int h = 0; h < 256; h++)
                acc = fmaf(grow[h], __bfloat162float(B2h[(size_t)n * 256 + h]) +
                                    __bfloat162float(B2l[(size_t)n * 256 + h]), acc);
            Wt[(size_t)gr * 64 + n] = acc;
        }
        __syncthreads();
    }
#endif
}

// ---------------------------------------------------------------------------
__global__ void transsplit_kernel(const float* __restrict__ src,
                                  __nv_bfloat16* __restrict__ dh,
                                  __nv_bfloat16* __restrict__ dl, int K, int Nc)
{
    int idx = blockIdx.x * 256 + threadIdx.x;
    if (idx < K * Nc) {
        int n = idx / K, k = idx % K;
        float v = src[(size_t)k * Nc + n];
        __nv_bfloat16 h = __float2bfloat16_rn(v);
        dh[idx] = h;
        dl[idx] = __float2bfloat16_rn(v - __bfloat162float(h));
    }
}

__global__ __launch_bounds__(512)
void spartial_kernel(const float* __restrict__ Hf, const float* __restrict__ Wt,
                     float* __restrict__ part, int N)
{
    __shared__ float ws[16 * MDIM];
    const int t = threadIdx.x;
    const int hq = t & 127, mq = t >> 7;
    const int blk = blockIdx.x;
    const int chunk = (N + SPBLK - 1) / SPBLK;
    const int rbeg = blk * chunk;
    const int rend = min(N, rbeg + chunk);

    float acc[2][16];
    #pragma unroll
    for (int j = 0; j < 2; j++)
        #pragma unroll
        for (int i = 0; i < 16; i++) acc[j][i] = 0.0f;

    for (int r = rbeg; r < rend; r += 16) {
        int nr = min(16, rend - r);
        __syncthreads();
        for (int i = t; i < nr * MDIM; i += 512)
            ws[i] = Wt[(size_t)r * MDIM + i];
        __syncthreads();
        int rr = 0;
        for (; rr + 2 <= nr; rr += 2) {
            float2 ha = *reinterpret_cast<const float2*>(&Hf[(size_t)(r + rr) * HDIM + hq * 2]);
            float2 hb = *reinterpret_cast<const float2*>(&Hf[(size_t)(r + rr + 1) * HDIM + hq * 2]);
            #pragma unroll
            for (int i = 0; i < 16; i++) {
                float wa = ws[rr * MDIM + mq * 16 + i];
                float wb = ws[(rr + 1) * MDIM + mq * 16 + i];
                acc[0][i] = fmaf(ha.x, wa, acc[0][i]);
                acc[1][i] = fmaf(ha.y, wa, acc[1][i]);
                acc[0][i] = fmaf(hb.x, wb, acc[0][i]);
                acc[1][i] = fmaf(hb.y, wb, acc[1][i]);
            }
        }
        for (; rr < nr; rr++) {
            float2 ha = *reinterpret_cast<const float2*>(&Hf[(size_t)(r + rr) * HDIM + hq * 2]);
            #pragma unroll
            for (int i = 0; i < 16; i++) {
                float wa = ws[rr * MDIM + mq * 16 + i];
                acc[0][i] = fmaf(ha.x, wa, acc[0][i]);
                acc[1][i] = fmaf(ha.y, wa, acc[1][i]);
            }
        }
    }
    #pragma unroll
    for (int j = 0; j < 2; j++) {
        float* p = part + (size_t)blk * HDIM * MDIM + (size_t)(hq * 2 + j) * MDIM + mq * 16;
        #pragma unroll
        for (int i4 = 0; i4 < 4; i4++)
            *reinterpret_cast<float4*>(&p[i4 * 4]) =
                make_float4(acc[j][i4 * 4], acc[j][i4 * 4 + 1], acc[j][i4 * 4 + 2], acc[j][i4 * 4 + 3]);
    }
}

__global__ __launch_bounds__(256)
void sfinal_kernel(const float* __restrict__ part,
                   __nv_bfloat16* __restrict__ sgh, __nv_bfloat16* __restrict__ sgl)
{
    int idx = blockIdx.x * 256 + threadIdx.x;  // h*64+m
    float s = 0.0f;
    for (int p = 0; p < SPBLK; p++)
        s += part[(size_t)p * HDIM * MDIM + idx];
    float g = gelu_f(s);
    __nv_bfloat16 h = __float2bfloat16_rn(g);
    sgh[idx] = h;
    sgl[idx] = __float2bfloat16_rn(g - __bfloat162float(h));
}

__global__ __launch_bounds__(256)
void meanpart_kernel(const float* __restrict__ X, float* __restrict__ part, int N)
{
    const int t = threadIdx.x, blk = blockIdx.x;
    const int chunk = (N + 255) / 256;
    const int rbeg = blk * chunk;
    const int rend = min(N, rbeg + chunk);
    float acc = 0.0f;
    for (int r = rbeg; r < rend; r++)
        acc += X[(size_t)r * HDIM + t];
    part[blk * HDIM + t] = acc;
}

__global__ __launch_bounds__(256)
void head_kernel(const float* __restrict__ part, const float* __restrict__ hw,
                 const float* __restrict__ hb, float* __restrict__ out, int N)
{
    __shared__ float s[HDIM];
    int t = threadIdx.x;
    float a = 0.0f;
    for (int p = 0; p < 256; p++) a += part[p * HDIM + t];
    s[t] = a * (1.0f / (float)N);
    __syncthreads();
    if (t < 64) {
        float o = hb[t];
        #pragma unroll 8
        for (int h = 0; h < HDIM; h++)
            o = fmaf(s[h], hw[h * 64 + t], o);
        out[t] = o;
    }
}

// ---------------------------------------------------------------------------
// Host
// ---------------------------------------------------------------------------
#define GSMEM(Nc) (BBASE + 2 * (Nc) * 256)
#define FSMEM     197632

template<bool GO, bool HB, bool TA, bool GA>
static void launch_g05(const float* A, const float* A2,
                       const __nv_bfloat16* Bh, const __nv_bfloat16* Bl,
                       const float* bias, float* C, int M, int K, int K1, int Nc)
{
    cudaFuncSetAttribute(gemm05_kernel<GO, HB, TA, GA>,
                         cudaFuncAttributeMaxDynamicSharedMemorySize, GSMEM(256));
    gemm05_kernel<GO, HB, TA, GA><<<(M + 127) / 128, NTH, GSMEM(Nc)>>>(
        A, A2, Bh, Bl, bias, C, M, K, K1, Nc);
}

extern "C" void kernel_launch(void* const* d_in, const int* in_sizes, int n_in,
                              void* d_out, int out_size)
{
    const float* x      = (const float*)d_in[0];
    const float* ff1_w0 = (const float*)d_in[2];
    const float* ff1_b0 = (const float*)d_in[3];
    const float* wA0    = (const float*)d_in[4];
    const float* wB0    = (const float*)d_in[5];
    const float* ff2_w0 = (const float*)d_in[6];
    const float* ff2_b0 = (const float*)d_in[7];
    const float* ff1_w1 = (const float*)d_in[8];
    const float* ff1_b1 = (const float*)d_in[9];
    const float* wA1    = (const float*)d_in[10];
    const float* wB1    = (const float*)d_in[11];
    const float* ff2_w1 = (const float*)d_in[12];
    const float* ff2_b1 = (const float*)d_in[13];
    const float* head_w = (const float*)d_in[14];
    const float* head_b = (const float*)d_in[15];
    float* out = (float*)d_out;

    const int N = in_sizes[0] / HDIM;

    float *pHf, *pG, *pX, *pWt, *pPart, *pMp;
    __nv_bfloat16 *pWh, *pWl, *pSgh, *pSgl;
    cudaGetSymbolAddress((void**)&pHf,   g_Hf);
    cudaGetSymbolAddress((void**)&pG,    g_G);
    cudaGetSymbolAddress((void**)&pX,    g_X);
    cudaGetSymbolAddress((void**)&pWt,   g_Wt);
    cudaGetSymbolAddress((void**)&pPart, g_part);
    cudaGetSymbolAddress((void**)&pMp,   g_mp);
    cudaGetSymbolAddress((void**)&pWh,   g_wh);
    cudaGetSymbolAddress((void**)&pWl,   g_wl);
    cudaGetSymbolAddress((void**)&pSgh,  g_sgh);
    cudaGetSymbolAddress((void**)&pSgl,  g_sgl);

    struct { const float* src; int off, K, Nc; } wp[8] = {
        {ff1_w0, W_FF1,          256, 256}, {wA0, W_WA,          256, 256},
        {wB0,    W_WB,           256,  64}, {ff2_w0, W_FF2,      512, 256},
        {ff1_w1, W_BLK + W_FF1,  256, 256}, {wA1, W_BLK + W_WA,  256, 256},
        {wB1,    W_BLK + W_WB,   256,  64}, {ff2_w1, W_BLK + W_FF2, 512, 256},
    };
    for (int i = 0; i < 8; i++) {
        int n = wp[i].K * wp[i].Nc;
        transsplit_kernel<<<(n + 255) / 256, 256>>>(wp[i].src, pWh + wp[i].off,
                                                    pWl + wp[i].off, wp[i].K, wp[i].Nc);
    }
    cudaFuncSetAttribute(gemmGW_kernel,
                         cudaFuncAttributeMaxDynamicSharedMemorySize, FSMEM);

    const float* Xin = x;
    const float* ff1b[2] = {ff1_b0, ff1_b1};
    const float* ff2b[2] = {ff2_b0, ff2_b1};
    for (int b = 0; b < 2; b++) {
        int wo = b * W_BLK;
        // Hf = gelu(X @ ff1 + b)
        launch_g05<true, true, false, false>(Xin, nullptr, pWh + wo + W_FF1, pWl + wo + W_FF1,
                                             ff1b[b], pHf, N, 256, 0, 256);
        // Wt = gelu(Hf @ wA) @ wB   (fused, G never hits HBM)
        gemmGW_kernel<<<(N + 127) / 128, NTH, FSMEM>>>(
            pHf, pWh + wo + W_WA, pWl + wo + W_WA,
            pWh + wo + W_WB, pWl + wo + W_WB, pWt, N);
        // S = Hf^T @ Wt (deterministic split-K), Sg = gelu(S) split-bf16
        spartial_kernel<<<SPBLK, 512>>>(pHf, pWt, pPart, N);
        sfinal_kernel<<<64, 256>>>(pPart, pSgh, pSgl);
        // P = gelu(Wt @ Sg^T)
        launch_g05<true, false, false, false>(pWt, nullptr, pSgh, pSgl,
                                              nullptr, pG, N, 64, 0, 256);
        // X = [P, gelu(Hf)] @ ff2 + b
        launch_g05<false, true, true, true>(pG, pHf, pWh + wo + W_FF2, pWl + wo + W_FF2,
                                            ff2b[b], pX, N, 512, 256, 256);
        Xin = pX;
    }

    meanpart_kernel<<<256, 256>>>(pX, pMp, N);
    head_kernel<<<1, 256>>>(pMp, head_w, head_b, out, N);
}